// round 7
// baseline (speedup 1.0000x reference)
#include <cuda_runtime.h>

#define TT 128   // decodelen
#define BB 512   // batch
#define EE 128   // entity size
#define NEVT 16  // lse accumulations (15 boundaries + terminal)
#define NB 4     // batches per block
#define L2E 1.4426950408889634f
#define LN2 0.6931471805599453f
#define QSTR 40   // floats per quarter slot (32 used + 8 pad)
#define BSTR 168  // floats per batch slot (4*40 + 8 pad)

__device__ float g_partial[BB];
__device__ unsigned int g_done;   // zero-init; restored to 0 every launch

// ---------------------------------------------------------------------------
__device__ __forceinline__ void ffma2(unsigned long long &d,
                                      unsigned long long a,
                                      unsigned long long b) {
    asm("fma.rn.f32x2 %0, %1, %2, %0;" : "+l"(d) : "l"(a), "l"(b));
}
__device__ __forceinline__ void fadd2(unsigned long long &d, unsigned long long a) {
    asm("add.rn.f32x2 %0, %0, %1;" : "+l"(d) : "l"(a));
}
__device__ __forceinline__ unsigned long long pack2(float lo, float hi) {
    unsigned long long r;
    asm("mov.b64 %0, {%1, %2};" : "=l"(r) : "f"(lo), "f"(hi));
    return r;
}
__device__ __forceinline__ float pairsum(unsigned long long a) {
    float lo, hi;
    asm("mov.b64 {%0, %1}, %2;" : "=f"(lo), "=f"(hi) : "l"(a));
    return lo + hi;
}
__device__ __forceinline__ float ex2(float x) {
    float r; asm("ex2.approx.ftz.f32 %0, %1;" : "=f"(r) : "f"(x)); return r;
}
__device__ __forceinline__ float lg2(float x) {
    float r; asm("lg2.approx.ftz.f32 %0, %1;" : "=f"(r) : "f"(x)); return r;
}

// ---------------------------------------------------------------------------
// 512 threads: thread (j = tid>>2, c = tid&3) owns k-quarter c of Q row j and
// batch b0+c downstream. Matvec: quarter-partials for all 4 batches, combined
// across the 4 row-threads by a 3-SHFL selected-operand butterfly. 4 warps per
// SMSP (occ 1, 16 warps) hides LDS/FFMA/MUFU latency. Lagged normalizer G
// keeps the lse math exact with no reduction on the critical path.
// ---------------------------------------------------------------------------
__global__ void __launch_bounds__(512, 1)
crf_kernel(const float* __restrict__ feats, const float* __restrict__ trans,
           float* __restrict__ out, int nblocks) {
    const int tid = threadIdx.x;
    const int j = tid >> 2, c = tid & 3, lane = tid & 31, wrp = tid >> 5;
    const int b0 = blockIdx.x * NB;

    __shared__ __align__(16) float PQ[2][NB * BSTR];      // P, double buffered
    __shared__ __align__(16) float wmbuf[2][NB][16];      // lagged warp maxes
    __shared__ float bmv[NB][NEVT][16], bsv[NB][NEVT][16];
    __shared__ float rsum[16];
    __shared__ unsigned s_last;

    // ---- feat prefetch first (long latency); batch b0+c, entity j ----
    const size_t bstr = (size_t)BB * EE;
    const float* fp = feats + (size_t)(b0 + c) * EE + j;
    float fA  = fp[bstr];        // t=1 (u=0)
    float fn  = fp[2 * bstr];    // t=2 (u=1)
    float fn2 = 0.0f;

    // ---- build quarter of Q row j (log2 domain); row max over full row ----
    const float4* row = (const float4*)(trans + j * EE);
    float m = -3.4e38f;
#pragma unroll
    for (int i = 0; i < 32; i++) {
        float4 v = row[i];
        m = fmaxf(m, fmaxf(fmaxf(v.x, v.y), fmaxf(v.z, v.w)));
    }
    unsigned long long q[16];
#pragma unroll
    for (int i = 0; i < 8; i++) {
        float4 v = row[c * 8 + i];
        q[2 * i]     = pack2(ex2((v.x - m) * L2E), ex2((v.y - m) * L2E));
        q[2 * i + 1] = pack2(ex2((v.z - m) * L2E), ex2((v.w - m) * L2E));
    }
    const float mt2 = m * L2E;
    const float tl2 = trans[(EE - 1) * EE + j] * L2E;     // transitions[-1][j]

    float Gu  = (b0 + c == 0) ? 0.0f : (-10000.0f * L2E);
    float Gm1 = Gu;
    if (lane < 4) {                       // lane==c here; init both parities
        wmbuf[0][lane][wrp] = Gu;
        wmbuf[1][lane][wrp] = Gu;
    }

    float P = ex2(fA * L2E);              // P for u=0 (fv_init uniform == G)
    float ly = 0.0f, ec = 0.0f;
    int t2 = 3, s2 = 2;                   // prefetch: t(u+2), (u+2) mod 7
    const int stidx = c * BSTR + (j >> 5) * QSTR + (j & 31);

#pragma unroll 1
    for (int u = 0; u < 112; u++) {
        PQ[u & 1][stidx] = P;
        __syncthreads();

        // ---- shadow work ----
        float Gn;
        {
            const float4* wb = (const float4*)wmbuf[(u + 1) & 1][c];
            float4 w0 = wb[0], w1 = wb[1], w2 = wb[2], w3 = wb[3];
            float a = fmaxf(fmaxf(w0.x, w0.y), fmaxf(w0.z, w0.w));
            float b = fmaxf(fmaxf(w1.x, w1.y), fmaxf(w1.z, w1.w));
            float d = fmaxf(fmaxf(w2.x, w2.y), fmaxf(w2.z, w2.w));
            float e = fmaxf(fmaxf(w3.x, w3.y), fmaxf(w3.z, w3.w));
            Gn = fmaxf(fmaxf(a, b), fmaxf(d, e));
        }
        if (u >= 1) {
            float fvp = Gm1 + mt2 + ly;   // lazy fv_{u-1}
            float wm = fvp;               // per-batch max over this warp's 8 j's
            wm = fmaxf(wm, __shfl_xor_sync(0xffffffffu, wm, 4));
            wm = fmaxf(wm, __shfl_xor_sync(0xffffffffu, wm, 8));
            wm = fmaxf(wm, __shfl_xor_sync(0xffffffffu, wm, 16));
            if (lane < 4) wmbuf[(u - 1) & 1][lane][wrp] = wm;
            if ((u % 7) == 0) {           // boundary e = u/7 - 1 (u = 7..105)
                int e = u / 7 - 1;
                float v = fvp + tl2;
                float mm = v;
                mm = fmaxf(mm, __shfl_xor_sync(0xffffffffu, mm, 4));
                mm = fmaxf(mm, __shfl_xor_sync(0xffffffffu, mm, 8));
                mm = fmaxf(mm, __shfl_xor_sync(0xffffffffu, mm, 16));
                float ss = ex2(v - mm);
                ss += __shfl_xor_sync(0xffffffffu, ss, 4);
                ss += __shfl_xor_sync(0xffffffffu, ss, 8);
                ss += __shfl_xor_sync(0xffffffffu, ss, 16);
                if (lane < 4) { bmv[lane][e][wrp] = mm; bsv[lane][e][wrp] = ss; }
            }
        }
        ec = ex2(fmaf(fn, L2E, Gu + mt2 - Gn));           // for step u+1
        if (u < 110) fn2 = fp[(size_t)t2 * bstr];         // f_{u+2}
        s2++; if (s2 == 7) { s2 = 0; t2 += 2; } else t2++;

        // ---- matvec: quarter-c partials for all 4 batches ----
        unsigned long long a0[2] = {0, 0}, a1[2] = {0, 0};
        unsigned long long a2[2] = {0, 0}, a3[2] = {0, 0};
        const float* PB = PQ[u & 1] + c * QSTR;
#pragma unroll
        for (int i = 0; i < 8; i++) {
            ulonglong2 v0 = *(const ulonglong2*)(PB + 0 * BSTR + 4 * i);
            ulonglong2 v1 = *(const ulonglong2*)(PB + 1 * BSTR + 4 * i);
            ulonglong2 v2 = *(const ulonglong2*)(PB + 2 * BSTR + 4 * i);
            ulonglong2 v3 = *(const ulonglong2*)(PB + 3 * BSTR + 4 * i);
            ffma2(a0[0], q[2 * i], v0.x); ffma2(a0[1], q[2 * i + 1], v0.y);
            ffma2(a1[0], q[2 * i], v1.x); ffma2(a1[1], q[2 * i + 1], v1.y);
            ffma2(a2[0], q[2 * i], v2.x); ffma2(a2[1], q[2 * i + 1], v2.y);
            ffma2(a3[0], q[2 * i], v3.x); ffma2(a3[1], q[2 * i + 1], v3.y);
        }
        fadd2(a0[0], a0[1]); fadd2(a1[0], a1[1]);
        fadd2(a2[0], a2[1]); fadd2(a3[0], a3[1]);
        float v0 = pairsum(a0[0]), v1 = pairsum(a1[0]);
        float v2 = pairsum(a2[0]), v3 = pairsum(a3[0]);

        // combine quarters (threads c=0..3 of row j are lanes c^*):
        // level 1 (xor 1): batch-c pair-sum and batch-(c^2) pair-sum
        float selA = (c == 0) ? v1 : (c == 1) ? v0 : (c == 2) ? v3 : v2;  // v[c^1]
        float selB = (c == 0) ? v3 : (c == 1) ? v2 : (c == 2) ? v1 : v0;  // v[c^3]
        float rA = __shfl_xor_sync(0xffffffffu, selA, 1);  // v_c(c^1)
        float rB = __shfl_xor_sync(0xffffffffu, selB, 1);  // v_{c^2}(c^1)
        float own  = (c == 0) ? v0 : (c == 1) ? v1 : (c == 2) ? v2 : v3;  // v[c]
        float othr = (c == 0) ? v2 : (c == 1) ? v3 : (c == 2) ? v0 : v1;  // v[c^2]
        float A = own + rA;           // batch c over quarters {c, c^1}
        float B = othr + rB;          // batch c^2 over quarters {c, c^1}
        float rC = __shfl_xor_sync(0xffffffffu, B, 2);     // batch c over {c^2, c^3}
        float y = A + rC;

        P  = y * ec;
        ly = lg2(y);
        Gm1 = Gu; Gu = Gn; fn = fn2;
    }

    // terminal partials from fv_111 = Gm1 + mt2 + ly
    {
        float v = Gm1 + mt2 + ly + tl2;
        float mm = v;
        mm = fmaxf(mm, __shfl_xor_sync(0xffffffffu, mm, 4));
        mm = fmaxf(mm, __shfl_xor_sync(0xffffffffu, mm, 8));
        mm = fmaxf(mm, __shfl_xor_sync(0xffffffffu, mm, 16));
        float ss = ex2(v - mm);
        ss += __shfl_xor_sync(0xffffffffu, ss, 4);
        ss += __shfl_xor_sync(0xffffffffu, ss, 8);
        ss += __shfl_xor_sync(0xffffffffu, ss, 16);
        if (lane < 4) { bmv[lane][NEVT - 1][wrp] = mm; bsv[lane][NEVT - 1][wrp] = ss; }
    }
    __syncthreads();

    // combine deferred partials: 64 threads = 16 events x 4 batches
    if (tid < 64) {
        int ev = tid & 15, bt = tid >> 4;
        float M = -3.4e38f;
#pragma unroll
        for (int w = 0; w < 16; w++) M = fmaxf(M, bmv[bt][ev][w]);
        float ss = 0.0f;
#pragma unroll
        for (int w = 0; w < 16; w++) ss += bsv[bt][ev][w] * ex2(bmv[bt][ev][w] - M);
        float l = M + lg2(ss);                 // per-event lse, log2 units
#pragma unroll
        for (int o = 1; o < 16; o <<= 1) l += __shfl_xor_sync(0xffffffffu, l, o);
        if (ev == 0) g_partial[b0 + bt] = l * LN2;
    }

    // ---- fused final reduction: last block sums all partials ----
    __threadfence();
    __syncthreads();
    if (tid == 0) {
        unsigned v = atomicAdd(&g_done, 1u);
        s_last = (v == (unsigned)(nblocks - 1)) ? 1u : 0u;
    }
    __syncthreads();
    if (s_last) {
        __threadfence();                       // acquire other blocks' partials
        float v = __ldcg(&g_partial[tid]);     // 512 threads, bypass L1
#pragma unroll
        for (int o = 16; o; o >>= 1) v += __shfl_xor_sync(0xffffffffu, v, o);
        if (lane == 0) rsum[wrp] = v;
        __syncthreads();
        if (tid == 0) {
            float tot = 0.0f;
#pragma unroll
            for (int w = 0; w < 16; w++) tot += rsum[w];
            out[0] = tot * (1.0f / (float)(BB * NEVT));
            g_done = 0;                        // restore for next graph replay
        }
    }
}

// ---------------------------------------------------------------------------
extern "C" void kernel_launch(void* const* d_in, const int* in_sizes, int n_in,
                              void* d_out, int out_size) {
    const float* feats = (const float*)d_in[0];
    const float* trans = (const float*)d_in[1];
    if (n_in >= 2 && in_sizes[0] == EE * EE) {   // defensive order check
        feats = (const float*)d_in[1];
        trans = (const float*)d_in[0];
    }
    crf_kernel<<<BB / NB, 512>>>(feats, trans, (float*)d_out, BB / NB);
}

// round 8
// speedup vs baseline: 1.7628x; 1.7628x over previous
#include <cuda_runtime.h>

#define TT 128
#define BB 512
#define EE 128
#define NEVT 16
#define NB 2              // batches per CTA
#define NBLK (BB / NB)    // 256 blocks
#define L2E 1.4426950408889634f
#define LN2 0.6931471805599453f
#define PSTR 168          // floats per batch slot in P buffer (4*40 + 8 pad)

__device__ float g_partial[BB];
__device__ unsigned int g_done;    // zero-init; restored to 0 each launch

// ---------------------------------------------------------------------------
__device__ __forceinline__ void ffma2(unsigned long long &d,
                                      unsigned long long a,
                                      unsigned long long b) {
    asm("fma.rn.f32x2 %0, %1, %2, %0;" : "+l"(d) : "l"(a), "l"(b));
}
__device__ __forceinline__ void fadd2(unsigned long long &d, unsigned long long a) {
    asm("add.rn.f32x2 %0, %0, %1;" : "+l"(d) : "l"(a));
}
__device__ __forceinline__ unsigned long long pack2(float lo, float hi) {
    unsigned long long r;
    asm("mov.b64 %0, {%1, %2};" : "=l"(r) : "f"(lo), "f"(hi));
    return r;
}
__device__ __forceinline__ float pairsum(unsigned long long a) {
    float lo, hi;
    asm("mov.b64 {%0, %1}, %2;" : "=f"(lo), "=f"(hi) : "l"(a));
    return lo + hi;
}
__device__ __forceinline__ float ex2(float x) {
    float r; asm("ex2.approx.ftz.f32 %0, %1;" : "=f"(r) : "f"(x)); return r;
}
__device__ __forceinline__ float lg2(float x) {
    float r; asm("lg2.approx.ftz.f32 %0, %1;" : "=f"(r) : "f"(x)); return r;
}

// ---------------------------------------------------------------------------
// 256 threads: thread (g = tid>>2, c = tid&3) holds Q rows {g, g+64} for
// k-quarter c (32 f32x2 regs). Each loaded P chunk feeds BOTH rows -> LDS:FFMA2
// ratio 1:4 (smem wavefronts were the R7 bottleneck at 67% L1). After a 3-SHFL
// combine the thread owns scalar state for (j = g + 64*(c>>1), batch c&1).
// Lagged normalizer G (lag-3 warp-max) keeps lse math exact with no reduction
// on the critical path; ONE barrier per step. 2 CTAs/SM, 4 warps/SMSP.
// ---------------------------------------------------------------------------
__global__ void __launch_bounds__(256, 2)
crf_kernel(const float* __restrict__ feats, const float* __restrict__ trans,
           float* __restrict__ out, int nblocks) {
    const int tid = threadIdx.x;
    const int g = tid >> 2, c = tid & 3;
    const int b = c & 1, r = c >> 1;
    const int lane = tid & 31, wrp = tid >> 5;     // 8 warps
    const int jown = g + 64 * r;                   // owned entity row
    const int b0 = blockIdx.x * NB;

    __shared__ __align__(16) float PQ[2][NB * PSTR];
    __shared__ __align__(16) float wmbuf[2][NB][8];
    __shared__ float bmv[NB][NEVT][8], bsv[NB][NEVT][8];
    __shared__ float rsum[8];
    __shared__ unsigned s_last;

    // ---- feat prefetch first (owned (jown, b0+b)) ----
    const size_t bstr = (size_t)BB * EE;
    const float* fp = feats + (size_t)(b0 + b) * EE + jown;
    float fA  = fp[bstr];       // t=1 (u=0)
    float fn  = fp[2 * bstr];   // t=2 (u=1)
    float fn2 = 0.0f;

    // ---- build Q rows {g, g+64}, quarter c (log2 domain) ----
    const float4* rowA = (const float4*)(trans + g * EE);
    const float4* rowB = (const float4*)(trans + (g + 64) * EE);
    float mA = -3.4e38f, mB = -3.4e38f;
#pragma unroll
    for (int i = 0; i < 32; i++) {
        float4 a = rowA[i], bb = rowB[i];
        mA = fmaxf(mA, fmaxf(fmaxf(a.x, a.y), fmaxf(a.z, a.w)));
        mB = fmaxf(mB, fmaxf(fmaxf(bb.x, bb.y), fmaxf(bb.z, bb.w)));
    }
    unsigned long long qA[16], qB[16];
#pragma unroll
    for (int i = 0; i < 8; i++) {
        float4 a = rowA[c * 8 + i], bb = rowB[c * 8 + i];
        qA[2 * i]     = pack2(ex2((a.x - mA) * L2E), ex2((a.y - mA) * L2E));
        qA[2 * i + 1] = pack2(ex2((a.z - mA) * L2E), ex2((a.w - mA) * L2E));
        qB[2 * i]     = pack2(ex2((bb.x - mB) * L2E), ex2((bb.y - mB) * L2E));
        qB[2 * i + 1] = pack2(ex2((bb.z - mB) * L2E), ex2((bb.w - mB) * L2E));
    }
    const float mtown = (r ? mB : mA) * L2E;            // row max of owned row
    const float tl2 = trans[(EE - 1) * EE + jown] * L2E; // transitions[-1][jown]

    float Gu  = (b0 + b == 0) ? 0.0f : (-10000.0f * L2E);
    float Gm1 = Gu;
    if (lane < 2) {     // lane==b for lanes 0,1; init both parities
        float gv = (b0 + lane == 0) ? 0.0f : (-10000.0f * L2E);
        wmbuf[0][lane][wrp] = gv;
        wmbuf[1][lane][wrp] = gv;
    }

    float P = ex2(fA * L2E);        // u=0: fv_init uniform == G
    float ly = 0.0f, ec = 0.0f;
    int t2 = 3, s2 = 2;             // prefetch: t(u+2), (u+2) mod 7
    const int stidx = b * PSTR + (jown >> 5) * 40 + (jown & 31);

#pragma unroll 1
    for (int u = 0; u < 112; u++) {
        PQ[u & 1][stidx] = P;
        __syncthreads();

        // ---- shadow work (off critical path) ----
        float Gn;
        {
            const float4* wb = (const float4*)wmbuf[(u + 1) & 1][b];
            float4 w0 = wb[0], w1 = wb[1];
            float a = fmaxf(fmaxf(w0.x, w0.y), fmaxf(w0.z, w0.w));
            float d = fmaxf(fmaxf(w1.x, w1.y), fmaxf(w1.z, w1.w));
            Gn = fmaxf(a, d);
        }
        if (u >= 1) {
            float fvp = Gm1 + mtown + ly;   // lazy fv_{u-1} (owned j,b)
            float wm = fvp;                 // per-b max over warp's 16 j's
            wm = fmaxf(wm, __shfl_xor_sync(0xffffffffu, wm, 2));
            wm = fmaxf(wm, __shfl_xor_sync(0xffffffffu, wm, 4));
            wm = fmaxf(wm, __shfl_xor_sync(0xffffffffu, wm, 8));
            wm = fmaxf(wm, __shfl_xor_sync(0xffffffffu, wm, 16));
            if (lane < 2) wmbuf[(u - 1) & 1][lane][wrp] = wm;
            if ((u % 7) == 0) {             // boundary e = u/7 - 1 (u=7..105)
                int e = u / 7 - 1;
                float v = fvp + tl2;
                float mm = v;
                mm = fmaxf(mm, __shfl_xor_sync(0xffffffffu, mm, 2));
                mm = fmaxf(mm, __shfl_xor_sync(0xffffffffu, mm, 4));
                mm = fmaxf(mm, __shfl_xor_sync(0xffffffffu, mm, 8));
                mm = fmaxf(mm, __shfl_xor_sync(0xffffffffu, mm, 16));
                float ss = ex2(v - mm);
                ss += __shfl_xor_sync(0xffffffffu, ss, 2);
                ss += __shfl_xor_sync(0xffffffffu, ss, 4);
                ss += __shfl_xor_sync(0xffffffffu, ss, 8);
                ss += __shfl_xor_sync(0xffffffffu, ss, 16);
                if (lane < 2) { bmv[lane][e][wrp] = mm; bsv[lane][e][wrp] = ss; }
            }
        }
        ec = ex2(fmaf(fn, L2E, Gu + mtown - Gn));        // for step u+1
        if (u < 110) fn2 = fp[(size_t)t2 * bstr];        // f_{u+2}
        s2++; if (s2 == 7) { s2 = 0; t2 += 2; } else t2++;

        // ---- matvec: rows {g,g+64} x batches {0,1}, quarter c ----
        unsigned long long aA0[2] = {0, 0}, aA1[2] = {0, 0};  // row g: b0,b1
        unsigned long long aB0[2] = {0, 0}, aB1[2] = {0, 0};  // row g+64
        const float* P0 = PQ[u & 1] + 0 * PSTR + c * 40;
        const float* P1 = PQ[u & 1] + 1 * PSTR + c * 40;
#pragma unroll
        for (int i = 0; i < 8; i++) {
            ulonglong2 v0 = *(const ulonglong2*)(P0 + 4 * i);
            ulonglong2 v1 = *(const ulonglong2*)(P1 + 4 * i);
            ffma2(aA0[0], qA[2 * i], v0.x); ffma2(aA0[1], qA[2 * i + 1], v0.y);
            ffma2(aB0[0], qB[2 * i], v0.x); ffma2(aB0[1], qB[2 * i + 1], v0.y);
            ffma2(aA1[0], qA[2 * i], v1.x); ffma2(aA1[1], qA[2 * i + 1], v1.y);
            ffma2(aB1[0], qB[2 * i], v1.x); ffma2(aB1[1], qB[2 * i + 1], v1.y);
        }
        fadd2(aA0[0], aA0[1]); fadd2(aB0[0], aB0[1]);
        fadd2(aA1[0], aA1[1]); fadd2(aB1[0], aB1[1]);
        float vA0 = pairsum(aA0[0]), vB0 = pairsum(aB0[0]);  // [row][batch]
        float vA1 = pairsum(aA1[0]), vB1 = pairsum(aB1[0]);

        // combine quarters across the 4 threads of group g:
        // round 1 (xor 1, flips b): send my partials for batch b^1
        float sA = b ? vA0 : vA1;          // v[rowA][b^1]
        float sB = b ? vB0 : vB1;          // v[rowB][b^1]
        float rA = __shfl_xor_sync(0xffffffffu, sA, 1);
        float rBv = __shfl_xor_sync(0xffffffffu, sB, 1);
        float wA = (b ? vA1 : vA0) + rA;   // rowA, my batch, quarters {c,c^1}
        float wB = (b ? vB1 : vB0) + rBv;  // rowB, my batch
        // round 2 (xor 2, flips r): send my non-owned row
        float sR = r ? wA : wB;
        float rR = __shfl_xor_sync(0xffffffffu, sR, 2);
        float y = (r ? wB : wA) + rR;      // full sum for (jown, b)

        P  = y * ec;
        ly = lg2(y);
        Gm1 = Gu; Gu = Gn; fn = fn2;
    }

    // terminal partials from fv_111 = Gm1 + mtown + ly
    {
        float v = Gm1 + mtown + ly + tl2;
        float mm = v;
        mm = fmaxf(mm, __shfl_xor_sync(0xffffffffu, mm, 2));
        mm = fmaxf(mm, __shfl_xor_sync(0xffffffffu, mm, 4));
        mm = fmaxf(mm, __shfl_xor_sync(0xffffffffu, mm, 8));
        mm = fmaxf(mm, __shfl_xor_sync(0xffffffffu, mm, 16));
        float ss = ex2(v - mm);
        ss += __shfl_xor_sync(0xffffffffu, ss, 2);
        ss += __shfl_xor_sync(0xffffffffu, ss, 4);
        ss += __shfl_xor_sync(0xffffffffu, ss, 8);
        ss += __shfl_xor_sync(0xffffffffu, ss, 16);
        if (lane < 2) { bmv[lane][NEVT - 1][wrp] = mm; bsv[lane][NEVT - 1][wrp] = ss; }
    }
    __syncthreads();

    // combine deferred partials: 32 threads = 16 events x 2 batches
    if (tid < 32) {
        int ev = tid & 15, bt = tid >> 4;
        float M = -3.4e38f;
#pragma unroll
        for (int w = 0; w < 8; w++) M = fmaxf(M, bmv[bt][ev][w]);
        float ss = 0.0f;
#pragma unroll
        for (int w = 0; w < 8; w++) ss += bsv[bt][ev][w] * ex2(bmv[bt][ev][w] - M);
        float l = M + lg2(ss);             // per-event lse, log2 units
#pragma unroll
        for (int o = 1; o < 16; o <<= 1) l += __shfl_xor_sync(0xffffffffu, l, o);
        if (ev == 0) g_partial[b0 + bt] = l * LN2;
    }

    // ---- fused final reduction: last block sums all partials ----
    __threadfence();
    __syncthreads();
    if (tid == 0) {
        unsigned v = atomicAdd(&g_done, 1u);
        s_last = (v == (unsigned)(nblocks - 1)) ? 1u : 0u;
    }
    __syncthreads();
    if (s_last) {
        __threadfence();
        float v = __ldcg(&g_partial[tid]) + __ldcg(&g_partial[tid + 256]);
#pragma unroll
        for (int o = 16; o; o >>= 1) v += __shfl_xor_sync(0xffffffffu, v, o);
        if (lane == 0) rsum[wrp] = v;
        __syncthreads();
        if (tid == 0) {
            float tot = 0.0f;
#pragma unroll
            for (int w = 0; w < 8; w++) tot += rsum[w];
            out[0] = tot * (1.0f / (float)(BB * NEVT));
            g_done = 0;                    // restore for next graph replay
        }
    }
}

// ---------------------------------------------------------------------------
extern "C" void kernel_launch(void* const* d_in, const int* in_sizes, int n_in,
                              void* d_out, int out_size) {
    const float* feats = (const float*)d_in[0];
    const float* trans = (const float*)d_in[1];
    if (n_in >= 2 && in_sizes[0] == EE * EE) {   // defensive order check
        feats = (const float*)d_in[1];
        trans = (const float*)d_in[0];
    }
    crf_kernel<<<NBLK, 256>>>(feats, trans, (float*)d_out, NBLK);
}